// round 5
// baseline (speedup 1.0000x reference)
#include <cuda_runtime.h>
#include <math.h>

#define D   128
#define NMAX 50000
#define GR  64      // rows per GEMM block

// ---- scratch (device globals; 16B-aligned for float4 / red.v4 access) ----
__device__ __align__(16) float g_T[NMAX * D];    // Ts = (h@W) * dinv[row]
__device__ __align__(16) float g_A[NMAX * D];    // conv1 accumulator / hidden H
__device__ int   g_deg[NMAX];
__device__ float g_dinv[NMAX];
__device__ __align__(16) float g_gate[D];
__device__ __align__(16) float g_hbias[D];

// ---------------------------------------------------------------- degrees
__global__ void k_deg_init(int n) {
    int i = blockIdx.x * blockDim.x + threadIdx.x;
    if (i < n) g_deg[i] = 1;                    // self-loop
}

__global__ void k_deg_count(const int* __restrict__ edst, int E, int n) {
    int i = blockIdx.x * blockDim.x + threadIdx.x;
    if (i < E) {
        int d = edst[i];
        if ((unsigned)d < (unsigned)n) atomicAdd(&g_deg[d], 1);
    }
}

__global__ void k_dinv(int n) {
    int i = blockIdx.x * blockDim.x + threadIdx.x;
    if (i < n) g_dinv[i] = rsqrtf((float)g_deg[i]);
}

// ---------------------------------------------------------------- hypernet
__global__ void k_gate(const float* __restrict__ ctx,
                       const float* __restrict__ Wg,
                       const float* __restrict__ bg,
                       const float* __restrict__ Wb) {
    __shared__ float c[64];
    int j = threadIdx.x;                        // 128 threads
    if (j < 64) c[j] = ctx[j];
    __syncthreads();
    float g = bg[j];
    float b = 0.f;
#pragma unroll
    for (int k = 0; k < 64; k++) {
        g += c[k] * Wg[k * D + j];
        b += c[k] * Wb[k * D + j];
    }
    g_gate[j]  = 1.f / (1.f + expf(-g));
    g_hbias[j] = b;
}

// ---------------------------------------------------------------- GEMM + row scale
// T[r][:] = (X[r][:] @ W) * dinv[r].  256 threads, 64 rows x 128 cols per block.
__global__ void k_gemm_scale(const float* __restrict__ X,
                             const float* __restrict__ W,
                             float* __restrict__ T, int n) {
    extern __shared__ float sm[];
    float* Ws = sm;              // D*D floats (64KB)
    float* Xs = sm + D * D;      // GR*D floats (32KB)
    int tid = threadIdx.x;
    int r0  = blockIdx.x * GR;

    const float4* W4  = (const float4*)W;
    float4*       Ws4 = (float4*)Ws;
#pragma unroll
    for (int i = 0; i < (D * D / 4) / 256; i++)     // 16 iters
        Ws4[tid + i * 256] = W4[tid + i * 256];

    const float4* X4  = (const float4*)X;
    float4*       Xs4 = (float4*)Xs;
#pragma unroll
    for (int i = 0; i < (GR * D / 4) / 256; i++) {  // 8 iters
        int idx = tid + i * 256;                    // float4 index in tile
        int gr  = r0 + (idx >> 5);                  // 32 float4 per row
        Xs4[idx] = (gr < n) ? X4[(size_t)r0 * 32 + idx]
                            : make_float4(0.f, 0.f, 0.f, 0.f);
    }
    __syncthreads();

    int tc = tid & 31;
    int tr = tid >> 5;
    float acc[8][4];
#pragma unroll
    for (int i = 0; i < 8; i++)
#pragma unroll
        for (int c = 0; c < 4; c++) acc[i][c] = 0.f;

#pragma unroll 4
    for (int k = 0; k < D; k++) {
        float4 w = ((const float4*)(Ws + k * D))[tc];
#pragma unroll
        for (int i = 0; i < 8; i++) {
            float xv = Xs[(tr * 8 + i) * D + k];    // broadcast within warp
            acc[i][0] += xv * w.x;
            acc[i][1] += xv * w.y;
            acc[i][2] += xv * w.z;
            acc[i][3] += xv * w.w;
        }
    }

#pragma unroll
    for (int i = 0; i < 8; i++) {
        int r = r0 + tr * 8 + i;
        if (r < n) {
            float di = g_dinv[r];
            float4 o = make_float4(acc[i][0] * di, acc[i][1] * di,
                                   acc[i][2] * di, acc[i][3] * di);
            ((float4*)(T + (size_t)r * D))[tc] = o;
        }
    }
}

// ---------------------------------------------------------------- copy (self-loop init)
__global__ void k_copy(const float4* __restrict__ src, float4* __restrict__ dst, int n4) {
    int i = blockIdx.x * blockDim.x + threadIdx.x;
    if (i < n4) dst[i] = src[i];
}

// ---------------------------------------------------------------- edge scatter
// one warp per edge; lane handles one float4 (4 cols). Vectorized L2 reduction.
__global__ void k_scatter(const int* __restrict__ esrc,
                          const int* __restrict__ edst,
                          const float* __restrict__ T,
                          float* __restrict__ A, int E, int n) {
    int g   = blockIdx.x * blockDim.x + threadIdx.x;
    int eid = g >> 5;
    if (eid >= E) return;
    int lane = g & 31;
    int s = __ldg(&esrc[eid]);
    int d = __ldg(&edst[eid]);
    if ((unsigned)s >= (unsigned)n || (unsigned)d >= (unsigned)n) return;
    float4 v = ((const float4*)(T + (size_t)s * D))[lane];
    float* q = A + (size_t)d * D + lane * 4;
    asm volatile("red.global.add.v4.f32 [%0], {%1,%2,%3,%4};"
                 :: "l"(q), "f"(v.x), "f"(v.y), "f"(v.z), "f"(v.w) : "memory");
}

// ---------------------------------------------------------------- epilogues
__global__ void k_finish1(float* __restrict__ A, const float* __restrict__ b1, int n) {
    int i = blockIdx.x * blockDim.x + threadIdx.x;  // float4 index
    if (i >= n * 32) return;
    int row = i >> 5, c4 = i & 31;
    float di = g_dinv[row];
    float4 v = ((float4*)A)[i];
    float4 b = ((const float4*)b1)[c4];
    v.x = v.x * di + b.x;  v.y = v.y * di + b.y;
    v.z = v.z * di + b.z;  v.w = v.w * di + b.w;
    v.x = v.x > 0.f ? v.x : 0.2f * v.x;
    v.y = v.y > 0.f ? v.y : 0.2f * v.y;
    v.z = v.z > 0.f ? v.z : 0.2f * v.z;
    v.w = v.w > 0.f ? v.w : 0.2f * v.w;
    ((float4*)A)[i] = v;
}

__global__ void k_finish2(float* __restrict__ O, const float* __restrict__ b2, int n) {
    int i = blockIdx.x * blockDim.x + threadIdx.x;  // float4 index
    if (i >= n * 32) return;
    int row = i >> 5, c4 = i & 31;
    float di = g_dinv[row];
    float4 v  = ((float4*)O)[i];
    float4 b  = ((const float4*)b2)[c4];
    float4 gt = ((const float4*)g_gate)[c4];
    float4 hb = ((const float4*)g_hbias)[c4];
    v.x = (v.x * di + b.x) * gt.x + hb.x;
    v.y = (v.y * di + b.y) * gt.y + hb.y;
    v.z = (v.z * di + b.z) * gt.z + hb.z;
    v.w = (v.w * di + b.w) * gt.w + hb.w;
    ((float4*)O)[i] = v;
}

// ----------------------------------------------------------------
extern "C" void kernel_launch(void* const* d_in, const int* in_sizes, int n_in,
                              void* d_out, int out_size) {
    const float* x    = (const float*)d_in[0];
    const float* ctx  = (const float*)d_in[1];
    const float* W1   = (const float*)d_in[2];
    const float* b1   = (const float*)d_in[3];
    const float* W2   = (const float*)d_in[4];
    const float* b2   = (const float*)d_in[5];
    const float* Wg   = (const float*)d_in[6];
    const float* bg   = (const float*)d_in[7];
    const float* Wb   = (const float*)d_in[8];
    const int*   ei   = (const int*)d_in[9];     // int32: JAX x64 disabled
    float*       out  = (float*)d_out;

    int N = in_sizes[0] / D;
    int E = in_sizes[9] / 2;
    const int* esrc = ei;
    const int* edst = ei + E;

    float *pT, *pA;
    cudaGetSymbolAddress((void**)&pT, g_T);
    cudaGetSymbolAddress((void**)&pA, g_A);

    size_t smem = (size_t)(D * D + GR * D) * sizeof(float);   // 96KB
    cudaFuncSetAttribute(k_gemm_scale,
                         cudaFuncAttributeMaxDynamicSharedMemorySize, (int)smem);

    int nbN  = (N + 255) / 256;
    int nbE  = (E + 255) / 256;
    int gblk = (N + GR - 1) / GR;
    int n4   = N * 32;                 // float4 count of an N x 128 tensor
    int nb4  = (n4 + 255) / 256;
    long long sth = (long long)E * 32; // one warp per edge
    int nbS  = (int)((sth + 255) / 256);

    // degrees + hypernet
    k_deg_init<<<nbN, 256>>>(N);
    k_deg_count<<<nbE, 256>>>(edst, E, N);
    k_dinv<<<nbN, 256>>>(N);
    k_gate<<<1, 128>>>(ctx, Wg, bg, Wb);

    // conv1: A = leaky( dinv .* (scatter(Ts) + Ts_self) + b1 )
    k_gemm_scale<<<gblk, 256, smem>>>(x, W1, pT, N);
    k_copy<<<nb4, 256>>>((const float4*)pT, (float4*)pA, n4);
    k_scatter<<<nbS, 256>>>(esrc, edst, pT, pA, E, N);
    k_finish1<<<nb4, 256>>>(pA, b1, N);

    // conv2: out = ( dinv .* (scatter(Ts) + Ts_self) + b2 ) * gate + hbias
    k_gemm_scale<<<gblk, 256, smem>>>(pA, W2, pT, N);
    k_copy<<<nb4, 256>>>((const float4*)pT, (float4*)out, n4);
    k_scatter<<<nbS, 256>>>(esrc, edst, pT, out, E, N);
    k_finish2<<<nb4, 256>>>(out, b2, N);
}

// round 6
// speedup vs baseline: 1.1251x; 1.1251x over previous
#include <cuda_runtime.h>
#include <math.h>

#define D     128
#define NMAX  50000
#define EMAX  800000
#define GR    64      // rows per GEMM block

// ---- scratch (device globals; 16B-aligned for float4 access) ----
__device__ __align__(16) float g_T[NMAX * D];    // Ts = (h@W) * dinv[row]
__device__ __align__(16) float g_A[NMAX * D];    // hidden H
__device__ int   g_deg[NMAX];                    // indeg + 1 (self-loop)
__device__ int   g_rowptr[NMAX];                 // CSR row starts (in-edges, excl. self)
__device__ int   g_pos[NMAX];                    // fill cursors
__device__ int   g_eidx[EMAX];                   // CSR column (source) indices
__device__ float g_dinv[NMAX];
__device__ __align__(16) float g_gate[D];
__device__ __align__(16) float g_hbias[D];

// ---------------------------------------------------------------- degrees
__global__ void k_deg_init(int n) {
    int i = blockIdx.x * blockDim.x + threadIdx.x;
    if (i < n) g_deg[i] = 1;                    // self-loop
}

__global__ void k_deg_count(const int* __restrict__ edst, int E, int n) {
    int i = blockIdx.x * blockDim.x + threadIdx.x;
    if (i < E) {
        int d = edst[i];
        if ((unsigned)d < (unsigned)n) atomicAdd(&g_deg[d], 1);
    }
}

// ---------------------------------------------------------------- scan: rowptr, cursors, dinv
// single block, 1024 threads; per-thread serial partial + Hillis-Steele over partials.
__global__ void k_scan(int n) {
    __shared__ int part[1024];
    int tid = threadIdx.x;
    int per = (n + 1023) >> 10;
    int base = tid * per;
    int s = 0;
    for (int i = 0; i < per; i++) {
        int r = base + i;
        if (r < n) s += g_deg[r] - 1;           // CSR counts exclude self
    }
    part[tid] = s;
    __syncthreads();
    for (int off = 1; off < 1024; off <<= 1) {
        int v = (tid >= off) ? part[tid - off] : 0;
        __syncthreads();
        part[tid] += v;
        __syncthreads();
    }
    int run = (tid == 0) ? 0 : part[tid - 1];
    for (int i = 0; i < per; i++) {
        int r = base + i;
        if (r < n) {
            g_rowptr[r] = run;
            g_pos[r]    = run;
            run += g_deg[r] - 1;
            g_dinv[r] = rsqrtf((float)g_deg[r]);
        }
    }
}

// ---------------------------------------------------------------- CSR fill
__global__ void k_csr_fill(const int* __restrict__ esrc,
                           const int* __restrict__ edst, int E, int n) {
    int i = blockIdx.x * blockDim.x + threadIdx.x;
    if (i >= E) return;
    int s = esrc[i];
    int d = edst[i];
    if ((unsigned)s >= (unsigned)n || (unsigned)d >= (unsigned)n) return;
    int slot = atomicAdd(&g_pos[d], 1);
    if (slot < EMAX) g_eidx[slot] = s;
}

// ---------------------------------------------------------------- hypernet (warp per column)
__global__ void k_gate(const float* __restrict__ ctx,
                       const float* __restrict__ Wg,
                       const float* __restrict__ bg,
                       const float* __restrict__ Wb) {
    int w    = (blockIdx.x * blockDim.x + threadIdx.x) >> 5;   // column 0..127
    int lane = threadIdx.x & 31;
    if (w >= D) return;
    float c0 = ctx[lane], c1 = ctx[lane + 32];
    float g = c0 * Wg[lane * D + w] + c1 * Wg[(lane + 32) * D + w];
    float b = c0 * Wb[lane * D + w] + c1 * Wb[(lane + 32) * D + w];
#pragma unroll
    for (int o = 16; o > 0; o >>= 1) {
        g += __shfl_down_sync(0xffffffffu, g, o);
        b += __shfl_down_sync(0xffffffffu, b, o);
    }
    if (lane == 0) {
        g_gate[w]  = 1.f / (1.f + __expf(-(g + bg[w])));
        g_hbias[w] = b;
    }
}

// ---------------------------------------------------------------- GEMM + row scale
// T[r][:] = (X[r][:] @ W) * dinv[r].  256 threads, 64 rows x 128 cols per block.
__global__ void k_gemm_scale(const float* __restrict__ X,
                             const float* __restrict__ W,
                             float* __restrict__ T, int n) {
    extern __shared__ float sm[];
    float* Ws = sm;              // D*D floats (64KB)
    float* Xs = sm + D * D;      // GR*D floats (32KB)
    int tid = threadIdx.x;
    int r0  = blockIdx.x * GR;

    const float4* W4  = (const float4*)W;
    float4*       Ws4 = (float4*)Ws;
#pragma unroll
    for (int i = 0; i < (D * D / 4) / 256; i++)     // 16 iters
        Ws4[tid + i * 256] = W4[tid + i * 256];

    const float4* X4  = (const float4*)X;
    float4*       Xs4 = (float4*)Xs;
#pragma unroll
    for (int i = 0; i < (GR * D / 4) / 256; i++) {  // 8 iters
        int idx = tid + i * 256;                    // float4 index in tile
        int gr  = r0 + (idx >> 5);                  // 32 float4 per row
        Xs4[idx] = (gr < n) ? X4[(size_t)r0 * 32 + idx]
                            : make_float4(0.f, 0.f, 0.f, 0.f);
    }
    __syncthreads();

    int tc = tid & 31;
    int tr = tid >> 5;
    float acc[8][4];
#pragma unroll
    for (int i = 0; i < 8; i++)
#pragma unroll
        for (int c = 0; c < 4; c++) acc[i][c] = 0.f;

#pragma unroll 4
    for (int k = 0; k < D; k++) {
        float4 w = ((const float4*)(Ws + k * D))[tc];
#pragma unroll
        for (int i = 0; i < 8; i++) {
            float xv = Xs[(tr * 8 + i) * D + k];    // broadcast within warp
            acc[i][0] += xv * w.x;
            acc[i][1] += xv * w.y;
            acc[i][2] += xv * w.z;
            acc[i][3] += xv * w.w;
        }
    }

#pragma unroll
    for (int i = 0; i < 8; i++) {
        int r = r0 + tr * 8 + i;
        if (r < n) {
            float di = g_dinv[r];
            float4 o = make_float4(acc[i][0] * di, acc[i][1] * di,
                                   acc[i][2] * di, acc[i][3] * di);
            ((float4*)(T + (size_t)r * D))[tc] = o;
        }
    }
}

// ---------------------------------------------------------------- fused CSR gather + epilogue
// one warp per destination row; lane handles 4 cols (float4).
// out[d] = epi( dinv[d] * (T[d] + sum_{s in in(d)} T[s]) + b )
// MODE 1: leaky_relu(0.2); MODE 2: *gate + hbias
template <int MODE>
__global__ void k_gather(const float* __restrict__ T,
                         float* __restrict__ Out,
                         const float* __restrict__ bvec, int n) {
    int w = (blockIdx.x * blockDim.x + threadIdx.x) >> 5;
    if (w >= n) return;
    int lane = threadIdx.x & 31;
    int beg = g_rowptr[w];
    int cnt = g_deg[w] - 1;

    float4 acc  = ((const float4*)(T + (size_t)w * D))[lane];   // self term
    float4 acc2 = make_float4(0.f, 0.f, 0.f, 0.f);

    int j = 0;
    while (j < cnt) {
        int chunk = min(cnt - j, 32);
        int myidx = (lane < chunk) ? g_eidx[beg + j + lane] : 0;
        int t = 0;
        for (; t + 1 < chunk; t += 2) {
            int s0 = __shfl_sync(0xffffffffu, myidx, t);
            int s1 = __shfl_sync(0xffffffffu, myidx, t + 1);
            float4 v0 = ((const float4*)(T + (size_t)s0 * D))[lane];
            float4 v1 = ((const float4*)(T + (size_t)s1 * D))[lane];
            acc.x  += v0.x; acc.y  += v0.y; acc.z  += v0.z; acc.w  += v0.w;
            acc2.x += v1.x; acc2.y += v1.y; acc2.z += v1.z; acc2.w += v1.w;
        }
        if (t < chunk) {
            int s0 = __shfl_sync(0xffffffffu, myidx, t);
            float4 v0 = ((const float4*)(T + (size_t)s0 * D))[lane];
            acc.x += v0.x; acc.y += v0.y; acc.z += v0.z; acc.w += v0.w;
        }
        j += chunk;
    }
    acc.x += acc2.x; acc.y += acc2.y; acc.z += acc2.z; acc.w += acc2.w;

    float di = g_dinv[w];
    float4 b = ((const float4*)bvec)[lane];
    float4 o;
    o.x = acc.x * di + b.x;
    o.y = acc.y * di + b.y;
    o.z = acc.z * di + b.z;
    o.w = acc.w * di + b.w;
    if (MODE == 1) {
        o.x = o.x > 0.f ? o.x : 0.2f * o.x;
        o.y = o.y > 0.f ? o.y : 0.2f * o.y;
        o.z = o.z > 0.f ? o.z : 0.2f * o.z;
        o.w = o.w > 0.f ? o.w : 0.2f * o.w;
    } else {
        float4 gt = ((const float4*)g_gate)[lane];
        float4 hb = ((const float4*)g_hbias)[lane];
        o.x = o.x * gt.x + hb.x;
        o.y = o.y * gt.y + hb.y;
        o.z = o.z * gt.z + hb.z;
        o.w = o.w * gt.w + hb.w;
    }
    ((float4*)(Out + (size_t)w * D))[lane] = o;
}

// ----------------------------------------------------------------
extern "C" void kernel_launch(void* const* d_in, const int* in_sizes, int n_in,
                              void* d_out, int out_size) {
    const float* x    = (const float*)d_in[0];
    const float* ctx  = (const float*)d_in[1];
    const float* W1   = (const float*)d_in[2];
    const float* b1   = (const float*)d_in[3];
    const float* W2   = (const float*)d_in[4];
    const float* b2   = (const float*)d_in[5];
    const float* Wg   = (const float*)d_in[6];
    const float* bg   = (const float*)d_in[7];
    const float* Wb   = (const float*)d_in[8];
    const int*   ei   = (const int*)d_in[9];     // int32 (JAX x64 disabled)
    float*       out  = (float*)d_out;

    int N = in_sizes[0] / D;
    int E = in_sizes[9] / 2;
    const int* esrc = ei;
    const int* edst = ei + E;

    float *pT, *pA;
    cudaGetSymbolAddress((void**)&pT, g_T);
    cudaGetSymbolAddress((void**)&pA, g_A);

    size_t smem = (size_t)(D * D + GR * D) * sizeof(float);   // 96KB
    cudaFuncSetAttribute(k_gemm_scale,
                         cudaFuncAttributeMaxDynamicSharedMemorySize, (int)smem);

    int nbN  = (N + 255) / 256;
    int nbE  = (E + 255) / 256;
    int gblk = (N + GR - 1) / GR;
    long long gth = (long long)N * 32;           // one warp per node
    int nbG  = (int)((gth + 255) / 256);

    // 1-4: degree + CSR build
    k_deg_init<<<nbN, 256>>>(N);
    k_deg_count<<<nbE, 256>>>(edst, E, N);
    k_scan<<<1, 1024>>>(N);
    k_csr_fill<<<nbE, 256>>>(esrc, edst, E, N);

    // 5: hypernet
    k_gate<<<16, 256>>>(ctx, Wg, bg, Wb);

    // 6-7: conv1  A = leaky( dinv .* (T_self + gather) + b1 )
    k_gemm_scale<<<gblk, 256, smem>>>(x, W1, pT, N);
    k_gather<1><<<nbG, 256>>>(pT, pA, b1, N);

    // 8-9: conv2  out = ( dinv .* (T_self + gather) + b2 ) * gate + hbias
    k_gemm_scale<<<gblk, 256, smem>>>(pA, W2, pT, N);
    k_gather<2><<<nbG, 256>>>(pT, out, b2, N);
}

// round 7
// speedup vs baseline: 1.2483x; 1.1095x over previous
#include <cuda_runtime.h>
#include <cuda_bf16.h>
#include <math.h>
#include <stdint.h>

#define D     128
#define NMAX  50000
#define EMAX  800000

// ---- scratch (device globals; 16B-aligned) ----
__device__ __align__(16) float    g_T[NMAX * D];
__device__ __align__(16) float    g_A[NMAX * D];
__device__ __align__(16) uint32_t g_Whi[2 * 8192];   // packed bf16 hi pairs, [m][n][kp]
__device__ __align__(16) uint32_t g_Wlo[2 * 8192];   // packed bf16 lo pairs
__device__ int   g_deg[NMAX];
__device__ int   g_rowptr[NMAX];
__device__ int   g_pos[NMAX];
__device__ int   g_eidx[EMAX];
__device__ float g_dinv[NMAX];
__device__ __align__(16) float g_gate[D];
__device__ __align__(16) float g_hbias[D];

// ---------------------------------------------------------------- degrees
__global__ void k_deg_init(int n) {
    int i = blockIdx.x * blockDim.x + threadIdx.x;
    if (i < n) g_deg[i] = 1;
}

__global__ void k_deg_count(const int* __restrict__ edst, int E, int n) {
    int i = blockIdx.x * blockDim.x + threadIdx.x;
    if (i < E) {
        int d = edst[i];
        if ((unsigned)d < (unsigned)n) atomicAdd(&g_deg[d], 1);
    }
}

// ---------------------------------------------------------------- scan
__global__ void k_scan(int n) {
    __shared__ int part[1024];
    int tid = threadIdx.x;
    int per = (n + 1023) >> 10;
    int base = tid * per;
    int s = 0;
    for (int i = 0; i < per; i++) {
        int r = base + i;
        if (r < n) s += g_deg[r] - 1;
    }
    part[tid] = s;
    __syncthreads();
    for (int off = 1; off < 1024; off <<= 1) {
        int v = (tid >= off) ? part[tid - off] : 0;
        __syncthreads();
        part[tid] += v;
        __syncthreads();
    }
    int run = (tid == 0) ? 0 : part[tid - 1];
    for (int i = 0; i < per; i++) {
        int r = base + i;
        if (r < n) {
            g_rowptr[r] = run;
            g_pos[r]    = run;
            run += g_deg[r] - 1;
            g_dinv[r] = rsqrtf((float)g_deg[r]);
        }
    }
}

// ---------------------------------------------------------------- CSR fill
__global__ void k_csr_fill(const int* __restrict__ esrc,
                           const int* __restrict__ edst, int E, int n) {
    int i = blockIdx.x * blockDim.x + threadIdx.x;
    if (i >= E) return;
    int s = esrc[i];
    int d = edst[i];
    if ((unsigned)s >= (unsigned)n || (unsigned)d >= (unsigned)n) return;
    int slot = atomicAdd(&g_pos[d], 1);
    if (slot < EMAX) g_eidx[slot] = s;
}

// ---------------------------------------------------------------- hypernet
__global__ void k_gate(const float* __restrict__ ctx,
                       const float* __restrict__ Wg,
                       const float* __restrict__ bg,
                       const float* __restrict__ Wb) {
    int w    = (blockIdx.x * blockDim.x + threadIdx.x) >> 5;
    int lane = threadIdx.x & 31;
    if (w >= D) return;
    float c0 = ctx[lane], c1 = ctx[lane + 32];
    float g = c0 * Wg[lane * D + w] + c1 * Wg[(lane + 32) * D + w];
    float b = c0 * Wb[lane * D + w] + c1 * Wb[(lane + 32) * D + w];
#pragma unroll
    for (int o = 16; o > 0; o >>= 1) {
        g += __shfl_down_sync(0xffffffffu, g, o);
        b += __shfl_down_sync(0xffffffffu, b, o);
    }
    if (lane == 0) {
        g_gate[w]  = 1.f / (1.f + __expf(-(g + bg[w])));
        g_hbias[w] = b;
    }
}

// ---------------------------------------------------------------- bf16 split helpers
__device__ __forceinline__ uint32_t bpack(__nv_bfloat16 a, __nv_bfloat16 b) {
    return (uint32_t)__bfloat16_as_ushort(a) | ((uint32_t)__bfloat16_as_ushort(b) << 16);
}
__device__ __forceinline__ void split2(float a, float b, uint32_t& hi, uint32_t& lo) {
    __nv_bfloat16 ha = __float2bfloat16(a);
    __nv_bfloat16 hb = __float2bfloat16(b);
    __nv_bfloat16 la = __float2bfloat16(a - __bfloat162float(ha));
    __nv_bfloat16 lb = __float2bfloat16(b - __bfloat162float(hb));
    hi = bpack(ha, hb);
    lo = bpack(la, lb);
}

// ---------------------------------------------------------------- W split/pack/transpose (one-time)
// Layout: g_Whi[m*8192 + n*64 + kp] = pack(bf16hi(W[2kp][n]), bf16hi(W[2kp+1][n]))
__global__ void k_prep_w(const float* __restrict__ W1, const float* __restrict__ W2) {
    int idx = blockIdx.x * blockDim.x + threadIdx.x;    // 0..16383
    if (idx >= 16384) return;
    int m  = idx >> 13;
    int r  = idx & 8191;
    int n  = r & 127;
    int kp = r >> 7;                                    // 0..63
    const float* W = m ? W2 : W1;
    float w0 = W[(2 * kp) * D + n];
    float w1 = W[(2 * kp + 1) * D + n];
    uint32_t hi, lo;
    split2(w0, w1, hi, lo);
    g_Whi[m * 8192 + n * 64 + kp] = hi;
    g_Wlo[m * 8192 + n * 64 + kp] = lo;
}

// ---------------------------------------------------------------- bf16x3 tensor-core GEMM
// T[r][:] = (X[r][:] @ W) * dinv[r],  via mma.sync.m16n8k16.bf16, 3-pass split:
// D = Xhi@Whi + Xhi@Wlo + Xlo@Whi   (lo*lo dropped, ~1.5e-5 rel)
#define PS 68      // padded row stride in words (64 pairs + 4 pad) -> conflict-free frags

__device__ __forceinline__ void mma16816(float* c, uint32_t a0, uint32_t a1,
                                         uint32_t a2, uint32_t a3,
                                         uint32_t b0, uint32_t b1) {
    asm volatile("mma.sync.aligned.m16n8k16.row.col.f32.bf16.bf16.f32 "
                 "{%0,%1,%2,%3}, {%4,%5,%6,%7}, {%8,%9}, {%0,%1,%2,%3};"
                 : "+f"(c[0]), "+f"(c[1]), "+f"(c[2]), "+f"(c[3])
                 : "r"(a0), "r"(a1), "r"(a2), "r"(a3), "r"(b0), "r"(b1));
}

__global__ void __launch_bounds__(256)
k_gemm_bf16x3(const float* __restrict__ X, int wsel,
              float* __restrict__ T, int n) {
    extern __shared__ uint32_t sm[];
    uint32_t* Xh = sm;                  // 128*PS
    uint32_t* Xl = Xh + 128 * PS;
    uint32_t* Wh = Xl + 128 * PS;
    uint32_t* Wl = Wh + 128 * PS;
    int tid = threadIdx.x;
    int r0  = blockIdx.x * 128;

    // copy packed W into padded smem (8192 words = 2048 uint4; 8 per thread)
    const uint32_t* gwh = g_Whi + wsel * 8192;
    const uint32_t* gwl = g_Wlo + wsel * 8192;
#pragma unroll
    for (int i = 0; i < 8; i++) {
        int q  = tid + i * 256;         // uint4 index
        int wb = q * 4;                 // word index
        int nn = wb >> 6, kp = wb & 63;
        *((uint4*)&Wh[nn * PS + kp]) = ((const uint4*)gwh)[q];
        *((uint4*)&Wl[nn * PS + kp]) = ((const uint4*)gwl)[q];
    }

    // load + split + pack X tile (128 rows x 128 cols)
#pragma unroll
    for (int i = 0; i < 16; i++) {
        int idx = tid + i * 256;        // float4 index, 0..4095
        int r   = idx >> 5;
        int c4  = idx & 31;             // float4 within row
        float4 v = make_float4(0.f, 0.f, 0.f, 0.f);
        int gr = r0 + r;
        if (gr < n) v = ((const float4*)X)[(size_t)gr * 32 + c4];
        uint32_t h01, l01, h23, l23;
        split2(v.x, v.y, h01, l01);
        split2(v.z, v.w, h23, l23);
        int kp = c4 * 2;                // pair index
        *((uint2*)&Xh[r * PS + kp]) = make_uint2(h01, h23);
        *((uint2*)&Xl[r * PS + kp]) = make_uint2(l01, l23);
    }
    __syncthreads();

    int wid  = tid >> 5;
    int lane = tid & 31;
    int g    = lane >> 2;
    int tig  = lane & 3;
    int rA   = wid * 16 + g;            // local row for a0/a2

    float acc[16][4];
#pragma unroll
    for (int t = 0; t < 16; t++)
#pragma unroll
        for (int c = 0; c < 4; c++) acc[t][c] = 0.f;

#pragma unroll
    for (int s = 0; s < 8; s++) {
        int kp = s * 8;
        uint32_t ah0 = Xh[rA * PS + kp + tig];
        uint32_t ah1 = Xh[(rA + 8) * PS + kp + tig];
        uint32_t ah2 = Xh[rA * PS + kp + tig + 4];
        uint32_t ah3 = Xh[(rA + 8) * PS + kp + tig + 4];
        uint32_t al0 = Xl[rA * PS + kp + tig];
        uint32_t al1 = Xl[(rA + 8) * PS + kp + tig];
        uint32_t al2 = Xl[rA * PS + kp + tig + 4];
        uint32_t al3 = Xl[(rA + 8) * PS + kp + tig + 4];
#pragma unroll
        for (int nt = 0; nt < 16; nt++) {
            int nb = nt * 8 + g;
            uint32_t bh0 = Wh[nb * PS + kp + tig];
            uint32_t bh1 = Wh[nb * PS + kp + tig + 4];
            uint32_t bl0 = Wl[nb * PS + kp + tig];
            uint32_t bl1 = Wl[nb * PS + kp + tig + 4];
            mma16816(acc[nt], ah0, ah1, ah2, ah3, bh0, bh1);
            mma16816(acc[nt], ah0, ah1, ah2, ah3, bl0, bl1);
            mma16816(acc[nt], al0, al1, al2, al3, bh0, bh1);
        }
    }

    // epilogue: scale by dinv, store
    int gr0 = r0 + wid * 16 + g;
    int gr1 = gr0 + 8;
    float d0 = (gr0 < n) ? g_dinv[gr0] : 0.f;
    float d1 = (gr1 < n) ? g_dinv[gr1] : 0.f;
#pragma unroll
    for (int nt = 0; nt < 16; nt++) {
        int c = nt * 8 + 2 * tig;
        if (gr0 < n) {
            float2 o = make_float2(acc[nt][0] * d0, acc[nt][1] * d0);
            *((float2*)&T[(size_t)gr0 * D + c]) = o;
        }
        if (gr1 < n) {
            float2 o = make_float2(acc[nt][2] * d1, acc[nt][3] * d1);
            *((float2*)&T[(size_t)gr1 * D + c]) = o;
        }
    }
}

// ---------------------------------------------------------------- fused CSR gather + epilogue
// one warp per destination row; lane handles 4 cols (float4). 4-way MLP.
template <int MODE>
__global__ void k_gather(const float* __restrict__ T,
                         float* __restrict__ Out,
                         const float* __restrict__ bvec, int n) {
    int w = (blockIdx.x * blockDim.x + threadIdx.x) >> 5;
    if (w >= n) return;
    int lane = threadIdx.x & 31;
    int beg = g_rowptr[w];
    int cnt = g_deg[w] - 1;

    float4 a0 = ((const float4*)(T + (size_t)w * D))[lane];   // self term
    float4 a1 = make_float4(0.f, 0.f, 0.f, 0.f);
    float4 a2 = make_float4(0.f, 0.f, 0.f, 0.f);
    float4 a3 = make_float4(0.f, 0.f, 0.f, 0.f);

    int j = 0;
    while (j < cnt) {
        int chunk = min(cnt - j, 32);
        int myidx = (lane < chunk) ? g_eidx[beg + j + lane] : 0;
        int t = 0;
        for (; t + 3 < chunk; t += 4) {
            int s0 = __shfl_sync(0xffffffffu, myidx, t);
            int s1 = __shfl_sync(0xffffffffu, myidx, t + 1);
            int s2 = __shfl_sync(0xffffffffu, myidx, t + 2);
            int s3 = __shfl_sync(0xffffffffu, myidx, t + 3);
            float4 v0 = ((const float4*)(T + (size_t)s0 * D))[lane];
            float4 v1 = ((const float4*)(T + (size_t)s1 * D))[lane];
            float4 v2 = ((const float4*)(T + (size_t)s2 * D))[lane];
            float4 v3 = ((const float4*)(T + (size_t)s3 * D))[lane];
            a0.x += v0.x; a0.y += v0.y; a0.z += v0.z; a0.w += v0.w;
            a1.x += v1.x; a1.y += v1.y; a1.z += v1.z; a1.w += v1.w;
            a2.x += v2.x; a2.y += v2.y; a2.z += v2.z; a2.w += v2.w;
            a3.x += v3.x; a3.y += v3.y; a3.z += v3.z; a3.w += v3.w;
        }
        for (; t < chunk; t++) {
            int s0 = __shfl_sync(0xffffffffu, myidx, t);
            float4 v0 = ((const float4*)(T + (size_t)s0 * D))[lane];
            a0.x += v0.x; a0.y += v0.y; a0.z += v0.z; a0.w += v0.w;
        }
        j += chunk;
    }
    a0.x += a1.x + a2.x + a3.x;
    a0.y += a1.y + a2.y + a3.y;
    a0.z += a1.z + a2.z + a3.z;
    a0.w += a1.w + a2.w + a3.w;

    float di = g_dinv[w];
    float4 b = ((const float4*)bvec)[lane];
    float4 o;
    o.x = a0.x * di + b.x;
    o.y = a0.y * di + b.y;
    o.z = a0.z * di + b.z;
    o.w = a0.w * di + b.w;
    if (MODE == 1) {
        o.x = o.x > 0.f ? o.x : 0.2f * o.x;
        o.y = o.y > 0.f ? o.y : 0.2f * o.y;
        o.z = o.z > 0.f ? o.z : 0.2f * o.z;
        o.w = o.w > 0.f ? o.w : 0.2f * o.w;
    } else {
        float4 gt = ((const float4*)g_gate)[lane];
        float4 hb = ((const float4*)g_hbias)[lane];
        o.x = o.x * gt.x + hb.x;
        o.y = o.y * gt.y + hb.y;
        o.z = o.z * gt.z + hb.z;
        o.w = o.w * gt.w + hb.w;
    }
    ((float4*)(Out + (size_t)w * D))[lane] = o;
}

// ----------------------------------------------------------------
extern "C" void kernel_launch(void* const* d_in, const int* in_sizes, int n_in,
                              void* d_out, int out_size) {
    const float* x    = (const float*)d_in[0];
    const float* ctx  = (const float*)d_in[1];
    const float* W1   = (const float*)d_in[2];
    const float* b1   = (const float*)d_in[3];
    const float* W2   = (const float*)d_in[4];
    const float* b2   = (const float*)d_in[5];
    const float* Wg   = (const float*)d_in[6];
    const float* bg   = (const float*)d_in[7];
    const float* Wb   = (const float*)d_in[8];
    const int*   ei   = (const int*)d_in[9];     // int32 (JAX x64 disabled)
    float*       out  = (float*)d_out;

    int N = in_sizes[0] / D;
    int E = in_sizes[9] / 2;
    const int* esrc = ei;
    const int* edst = ei + E;

    float *pT, *pA;
    cudaGetSymbolAddress((void**)&pT, g_T);
    cudaGetSymbolAddress((void**)&pA, g_A);

    int smemG = 4 * 128 * PS * sizeof(uint32_t);          // 139264 B
    cudaFuncSetAttribute(k_gemm_bf16x3,
                         cudaFuncAttributeMaxDynamicSharedMemorySize, smemG);

    int nbN  = (N + 255) / 256;
    int nbE  = (E + 255) / 256;
    int gblk = (N + 127) / 128;
    long long gth = (long long)N * 32;
    int nbG  = (int)((gth + 255) / 256);

    // degree + CSR build + packed weights + hypernet
    k_deg_init<<<nbN, 256>>>(N);
    k_deg_count<<<nbE, 256>>>(edst, E, N);
    k_scan<<<1, 1024>>>(N);
    k_csr_fill<<<nbE, 256>>>(esrc, edst, E, N);
    k_prep_w<<<64, 256>>>(W1, W2);
    k_gate<<<16, 256>>>(ctx, Wg, bg, Wb);

    // conv1: A = leaky( dinv .* (T_self + gather) + b1 )
    k_gemm_bf16x3<<<gblk, 256, smemG>>>(x, 0, pT, N);
    k_gather<1><<<nbG, 256>>>(pT, pA, b1, N);

    // conv2: out = ( dinv .* (T_self + gather) + b2 ) * gate + hbias
    k_gemm_bf16x3<<<gblk, 256, smemG>>>(pA, 1, pT, N);
    k_gather<2><<<nbG, 256>>>(pT, out, b2, N);
}